// round 16
// baseline (speedup 1.0000x reference)
#include <cuda_runtime.h>
#include <cuda_fp16.h>
#include <math.h>
#include <float.h>
#include <stdint.h>

#define BB   2
#define QN   30
#define WAYS 5
#define SHOTS 5
#define TOPK 5
#define DIMC 64
#define HWC  441
#define HWP  448
#define NSUP (WAYS*SHOTS)
#define LFE  15
#define SHW  (SHOTS*HWC)   // 2205
#define NTILE 7

// ---------------- scratch ----------------
__device__ __align__(16) __half g_qnH [BB*QN*DIMC*HWP];    // [n][d][perm16(h)] fp16 (kchan)
__device__ __align__(16) __half g_snH [BB*NSUP*DIMC*HWP];
__device__ __align__(16) __half g_qnTH[BB*QN*HWC*DIMC];    // [n][h][perm64(d)] fp16 (kpix)
__device__ __align__(16) __half g_snTH[BB*NSUP*HWC*DIMC];
__device__ float g_qpool[BB*QN*DIMC];
__device__ float g_spool[BB*NSUP*DIMC];
__device__ float g_feats[BB*QN*LFE];
__device__ float g_pix[BB*QN*WAYS*NTILE];
__device__ float g_chc[BB*QN*WAYS*4*DIMC*TOPK];

// fp16 k-perm within one 16-group (kchan layout)
__device__ __forceinline__ int perm16(int k) {
    return 4*((k >> 1) & 3) + 2*((k >> 3) & 1) + (k & 1);
}
// kpix 64-wide perm with ks-pairing
__device__ __forceinline__ int perm64(int k) {
    int ks = k >> 4, p = ks >> 1, e = ks & 1, r = k & 15;
    return 32*p + 8*((r >> 1) & 3) + 4*e + (2*((r >> 3) & 1) + (r & 1));
}

__device__ __forceinline__ void mma_f16(float &c0, float &c1, float &c2, float &c3,
                                        uint32_t a0, uint32_t a1, uint32_t a2, uint32_t a3,
                                        uint32_t b0, uint32_t b1) {
    asm("mma.sync.aligned.m16n8k16.row.col.f32.f16.f16.f32 "
        "{%0,%1,%2,%3}, {%4,%5,%6,%7}, {%8,%9}, {%0,%1,%2,%3};"
        : "+f"(c0), "+f"(c1), "+f"(c2), "+f"(c3)
        : "r"(a0), "r"(a1), "r"(a2), "r"(a3), "r"(b0), "r"(b1));
}
__device__ __forceinline__ void mma_f16_z(float &c0, float &c1, float &c2, float &c3,
                                          uint32_t a0, uint32_t a1, uint32_t a2, uint32_t a3,
                                          uint32_t b0, uint32_t b1) {
    asm("mma.sync.aligned.m16n8k16.row.col.f32.f16.f16.f32 "
        "{%0,%1,%2,%3}, {%4,%5,%6,%7}, {%8,%9}, {%10,%11,%12,%13};"
        : "=f"(c0), "=f"(c1), "=f"(c2), "=f"(c3)
        : "r"(a0), "r"(a1), "r"(a2), "r"(a3), "r"(b0), "r"(b1),
          "f"(0.f), "f"(0.f), "f"(0.f), "f"(0.f));
}
__device__ __forceinline__ void cp_async16(uint32_t dst, const void* src) {
    asm volatile("cp.async.cg.shared.global [%0], [%1], 16;" :: "r"(dst), "l"(src));
}
__device__ __forceinline__ void cp_commit() {
    asm volatile("cp.async.commit_group;");
}

__device__ __forceinline__ void ins5(float (&t)[TOPK], float v) {
    if (v > t[TOPK-1]) {
        float x = v;
        #pragma unroll
        for (int i = 0; i < TOPK; i++) {
            float hi = fmaxf(t[i], x);
            x = fminf(t[i], x);
            t[i] = hi;
        }
    }
}

// ---------------- L2-normalize + mean-pool + fp16 perm writes ----------------
template<int IS_S>
__global__ void __launch_bounds__(256) knorm_kernel(const float* __restrict__ x) {
    const int n = blockIdx.x;
    __half* __restrict__ xo = (IS_S ? g_snH  : g_qnH)  + (size_t)n * DIMC * HWP;
    __half* __restrict__ xT = (IS_S ? g_snTH : g_qnTH) + (size_t)n * HWC * DIMC;
    float* __restrict__ pool = (IS_S ? g_spool : g_qpool) + n * DIMC;
    const float* __restrict__ xr = x + (size_t)n * DIMC * HWC;
    __shared__ float inv[DIMC];
    __shared__ float tile[32][65];
    const int t = threadIdx.x, warp = t >> 5, lane = t & 31;

    for (int d = warp; d < DIMC; d += 8) {
        const float* row = xr + d * HWC;
        float ss = 0.f, sm = 0.f;
        for (int h = lane; h < HWC; h += 32) {
            float v = row[h];
            ss = fmaf(v, v, ss);
            sm += v;
        }
        #pragma unroll
        for (int o = 16; o; o >>= 1) {
            ss += __shfl_xor_sync(0xffffffffu, ss, o);
            sm += __shfl_xor_sync(0xffffffffu, sm, o);
        }
        if (lane == 0) {
            inv[d] = 1.0f / sqrtf(ss);
            pool[d] = sm * (1.0f / HWC);
        }
    }
    __syncthreads();

    for (int h0 = 0; h0 < HWP; h0 += 32) {
        #pragma unroll
        for (int p = 0; p < 8; p++) {
            int d = (t >> 5) + p * 8, hh = t & 31, h = h0 + hh;
            float v = (h < HWC) ? xr[d * HWC + h] * inv[d] : 0.f;
            int ph = (hh & 16) | perm16(hh & 15);
            xo[d * HWP + h0 + ph] = __float2half_rn(v);
            tile[hh][d] = v;
        }
        __syncthreads();
        if (h0 < HWC) {
            #pragma unroll
            for (int p = 0; p < 8; p++) {
                int d = t & 63, hh = (t >> 6) + p * 4, h = h0 + hh;
                if (h < HWC) xT[(size_t)h * DIMC + perm64(d)] = __float2half_rn(tile[hh][d]);
            }
        }
        __syncthreads();
    }
}

// ---------------- prototypes + cosine logits (fp32 pools) ----------------
__global__ void __launch_bounds__(256) kcos_kernel() {
    const int b = blockIdx.x, t = threadIdx.x;
    __shared__ float proto[WAYS * DIMC];
    __shared__ float pin[WAYS], qin[QN];
    for (int i = t; i < WAYS * DIMC; i += 256) {
        int w = i / DIMC, d = i - w * DIMC;
        float s = 0.f;
        #pragma unroll
        for (int k = 0; k < SHOTS; k++)
            s += g_spool[(b*NSUP + w*SHOTS + k)*DIMC + d];
        proto[i] = s * (1.0f / SHOTS);
    }
    __syncthreads();
    for (int i = t; i < WAYS + QN; i += 256) {
        if (i < WAYS) {
            float ss = 0.f;
            for (int d = 0; d < DIMC; d++) { float v = proto[i*DIMC + d]; ss = fmaf(v, v, ss); }
            pin[i] = 1.0f / sqrtf(ss);
        } else {
            int q = i - WAYS;
            float ss = 0.f;
            for (int d = 0; d < DIMC; d++) { float v = g_qpool[(b*QN + q)*DIMC + d]; ss = fmaf(v, v, ss); }
            qin[q] = 1.0f / sqrtf(ss);
        }
    }
    __syncthreads();
    for (int i = t; i < QN * WAYS; i += 256) {
        int q = i / WAYS, w = i - q * WAYS;
        float dot = 0.f;
        for (int d = 0; d < DIMC; d++)
            dot = fmaf(g_qpool[(b*QN + q)*DIMC + d], proto[w*DIMC + d], dot);
        g_feats[(b*QN + q)*LFE + w] = dot * qin[q] * pin[w];
    }
}

// ---------------- channel-level sim (R12 winner, 49.5us) ----------------
__global__ void __launch_bounds__(256) kchan_kernel() {
    const int w = blockIdx.x >> 2, quarter = blockIdx.x & 3;
    const int q = blockIdx.y, b = blockIdx.z;
    __shared__ __align__(16) __half AB[2][144][72];
    const int t = threadIdx.x, lane = t & 31, wid = t >> 5;
    const int wm = wid >> 1, wn = wid & 1;
    const int mrow = wm * 16 + (lane >> 2);
    const int fcol = 4 * (lane & 3);
    const __half* __restrict__ qbase = g_qnH + (size_t)(b*QN + q) * DIMC * HWP;
    const __half* __restrict__ sbase = g_snH + (size_t)(b*NSUP + w*SHOTS) * DIMC * HWP;
    const int jbase = quarter * 80;

    float c[5][4];
    #pragma unroll
    for (int nt = 0; nt < 5; nt++)
        #pragma unroll
        for (int i = 0; i < 4; i++) c[nt][i] = 0.f;

    auto fill = [&](int buf, int h0) {
        for (int idx = t; idx < 1152; idx += 256) {
            const __half* src;
            int row, seg;
            if (idx < 512) {
                row = idx >> 3; seg = idx & 7;
                src = qbase + (size_t)row * HWP + h0 + seg * 8;
            } else {
                int r = idx - 512;
                int jl = r >> 3; seg = r & 7;
                int j = jbase + jl;
                int shot = j >> 6, dd = j & 63;
                row = 64 + jl;
                src = sbase + (size_t)(shot*DIMC + dd) * HWP + h0 + seg * 8;
            }
            cp_async16((uint32_t)__cvta_generic_to_shared(&AB[buf][row][seg*8]), src);
        }
        cp_commit();
    };

    fill(0, 0);
    for (int it = 0; it < 7; it++) {
        const int cur = it & 1;
        __syncthreads();
        if (it < 6) {
            fill(cur ^ 1, (it + 1) * 64);
            asm volatile("cp.async.wait_group 1;");
        } else {
            asm volatile("cp.async.wait_group 0;");
        }
        __syncthreads();
        #pragma unroll
        for (int ks = 0; ks < 4; ks++) {
            uint2 alo = *(const uint2*)&AB[cur][mrow    ][ks*16 + fcol];
            uint2 ahi = *(const uint2*)&AB[cur][mrow + 8][ks*16 + fcol];
            #pragma unroll
            for (int nt = 0; nt < 5; nt++) {
                uint2 bb = *(const uint2*)&AB[cur][64 + wn*40 + nt*8 + (lane>>2)][ks*16 + fcol];
                mma_f16(c[nt][0], c[nt][1], c[nt][2], c[nt][3],
                        alo.x, ahi.x, alo.y, ahi.y, bb.x, bb.y);
            }
        }
    }

    float top[2][TOPK];
    #pragma unroll
    for (int r = 0; r < 2; r++)
        #pragma unroll
        for (int k = 0; k < TOPK; k++) top[r][k] = -FLT_MAX;
    #pragma unroll
    for (int nt = 0; nt < 5; nt++) {
        ins5(top[0], c[nt][0]); ins5(top[0], c[nt][1]);
        ins5(top[1], c[nt][2]); ins5(top[1], c[nt][3]);
    }
    #pragma unroll
    for (int off = 1; off <= 2; off <<= 1) {
        #pragma unroll
        for (int r = 0; r < 2; r++) {
            float other[TOPK];
            #pragma unroll
            for (int k = 0; k < TOPK; k++)
                other[k] = __shfl_xor_sync(0xffffffffu, top[r][k], off);
            #pragma unroll
            for (int k = 0; k < TOPK; k++) ins5(top[r], other[k]);
        }
    }

    __syncthreads();
    float (*cand)[10] = (float(*)[10])&AB[0][0][0];
    if ((lane & 3) == 0) {
        #pragma unroll
        for (int r = 0; r < 2; r++) {
            int row = mrow + r * 8;
            #pragma unroll
            for (int k = 0; k < TOPK; k++)
                cand[row][wn*TOPK + k] = top[r][k];
        }
    }
    __syncthreads();
    if (t < DIMC) {
        float t5[TOPK];
        #pragma unroll
        for (int k = 0; k < TOPK; k++) t5[k] = -FLT_MAX;
        #pragma unroll
        for (int i = 0; i < 10; i++) ins5(t5, cand[t][i]);
        float* dst = g_chc + ((size_t)(((b*QN + q)*WAYS + w)*4 + quarter))*DIMC*TOPK + t*TOPK;
        #pragma unroll
        for (int k = 0; k < TOPK; k++) dst[k] = t5[k];
    }
}

// ---------------- merge 4 quarter top-5s per d, sum over d -> sim_l ----------------
__global__ void __launch_bounds__(64) kmerge_kernel() {
    const int bqw = blockIdx.x;
    const int d = threadIdx.x;
    const float* base = g_chc + (size_t)bqw * 4 * DIMC * TOPK;
    float t5[TOPK];
    #pragma unroll
    for (int k = 0; k < TOPK; k++) t5[k] = -FLT_MAX;
    #pragma unroll
    for (int qt = 0; qt < 4; qt++)
        #pragma unroll
        for (int k = 0; k < TOPK; k++)
            ins5(t5, base[(qt*DIMC + d)*TOPK + k]);
    float s = t5[0] + t5[1] + t5[2] + t5[3] + t5[4];
    __shared__ float red[2];
    #pragma unroll
    for (int o = 16; o; o >>= 1) s += __shfl_xor_sync(0xffffffffu, s, o);
    if ((d & 31) == 0) red[d >> 5] = s;
    __syncthreads();
    if (d == 0) {
        int bq = bqw / WAYS, w = bqw % WAYS;
        g_feats[bq*LFE + WAYS + w] = red[0] + red[1];
    }
}

// ---------------- pixel-level sim v5: 2 m-tiles/warp, stride-96 conflict-free smem ----------------
// Warps: wm in {0,1} owns m16-tiles {2wm, 2wm+1} (A frags in regs); wn in {0..3} owns 16 cols.
// Each B LDS.128 feeds 4 MMAs; B duplication across warps halved (x2 instead of x4).
#define PIXSTR 96
__global__ void __launch_bounds__(256) kpix_kernel() {
    const int tile = blockIdx.x;
    const int w = blockIdx.y;
    const int bq = blockIdx.z;
    const int b = bq / QN;
    __shared__ __align__(16) __half SM[3][64][PIXSTR];
    __shared__ float red[2];
    const int t = threadIdx.x, lane = t & 31, wid = t >> 5;
    const int wm = wid >> 2, wn = wid & 3;
    const int qrow = lane >> 2;
    const int pcol = 8 * (lane & 3);
    const int h0 = tile * 64;
    const __half* __restrict__ qT = g_qnTH + (size_t)bq * HWC * DIMC;
    const __half* __restrict__ sT = g_snTH + (size_t)(b*NSUP + w*SHOTS) * HWC * DIMC;

    auto fillB = [&](int buf, int cb) {
        #pragma unroll
        for (int i = 0; i < 2; i++) {
            int idx = t + i * 256;
            int n = idx >> 3, seg = idx & 7;
            int j = cb + n;
            int jj = (j < SHW) ? j : 0;
            int shot = jj / HWC;
            int h2 = jj - shot * HWC;
            const __half* src = sT + (size_t)(shot*HWC + h2) * DIMC + seg * 8;
            cp_async16((uint32_t)__cvta_generic_to_shared(&SM[buf][n][seg*8]), src);
        }
        cp_commit();
    };

    // prologue: A -> SM[2], B0 -> SM[0], B1 -> SM[1]
    #pragma unroll
    for (int i = 0; i < 2; i++) {
        int idx = t + i * 256;
        int m = idx >> 3, seg = idx & 7;
        int h = h0 + m;
        const __half* src = qT + (size_t)((h < HWC) ? h : 0) * DIMC + seg * 8;
        cp_async16((uint32_t)__cvta_generic_to_shared(&SM[2][m][seg*8]), src);
    }
    cp_commit();
    fillB(0, 0);
    fillB(1, 64);
    asm volatile("cp.async.wait_group 2;");          // A ready
    __syncthreads();

    // A fragments: [tile T][row-half r][ks-pair p]
    uint4 aF[2][2][2];
    #pragma unroll
    for (int T = 0; T < 2; T++)
        #pragma unroll
        for (int r = 0; r < 2; r++)
            #pragma unroll
            for (int p = 0; p < 2; p++)
                aF[T][r][p] = *(const uint4*)&SM[2][32*wm + 16*T + 8*r + qrow][32*p + pcol];

    float top[2][2][TOPK];                           // [T][r]
    #pragma unroll
    for (int T = 0; T < 2; T++)
        #pragma unroll
        for (int r = 0; r < 2; r++)
            #pragma unroll
            for (int k = 0; k < TOPK; k++) top[T][r][k] = -FLT_MAX;

    for (int it = 0; it < 35; it++) {
        const int cur = it % 3;
        if (it < 34) asm volatile("cp.async.wait_group 1;");
        else         asm volatile("cp.async.wait_group 0;");
        __syncthreads();                              // aF extraction + prev reads of (it+2)%3 done
        if (it + 2 <= 34) fillB((it + 2) % 3, (it + 2) * 64);

        float c[2][2][4];                             // [T][nt]
        #pragma unroll
        for (int p = 0; p < 2; p++) {
            #pragma unroll
            for (int nt = 0; nt < 2; nt++) {
                uint4 bb = *(const uint4*)&SM[cur][wn*16 + nt*8 + qrow][32*p + pcol];
                #pragma unroll
                for (int T = 0; T < 2; T++) {
                    uint4 aLo = aF[T][0][p], aHi = aF[T][1][p];
                    float* cc = c[T][nt];
                    if (p == 0)
                        mma_f16_z(cc[0], cc[1], cc[2], cc[3],
                                  aLo.x, aHi.x, aLo.y, aHi.y, bb.x, bb.y);
                    else
                        mma_f16(cc[0], cc[1], cc[2], cc[3],
                                aLo.x, aHi.x, aLo.y, aHi.y, bb.x, bb.y);
                    mma_f16(cc[0], cc[1], cc[2], cc[3],
                            aLo.z, aHi.z, aLo.w, aHi.w, bb.z, bb.w);
                }
            }
        }

        if (it < 34) {
            #pragma unroll
            for (int T = 0; T < 2; T++)
                #pragma unroll
                for (int nt = 0; nt < 2; nt++) {
                    ins5(top[T][0], c[T][nt][0]); ins5(top[T][0], c[T][nt][1]);
                    ins5(top[T][1], c[T][nt][2]); ins5(top[T][1], c[T][nt][3]);
                }
        } else {
            const int cb = 34 * 64;
            #pragma unroll
            for (int T = 0; T < 2; T++)
                #pragma unroll
                for (int nt = 0; nt < 2; nt++) {
                    int col0 = cb + wn*16 + nt*8 + 2*(lane & 3);
                    if (col0 < SHW)     { ins5(top[T][0], c[T][nt][0]); ins5(top[T][1], c[T][nt][2]); }
                    if (col0 + 1 < SHW) { ins5(top[T][0], c[T][nt][1]); ins5(top[T][1], c[T][nt][3]); }
                }
        }
    }

    // quad merge (4 lanes share each row)
    #pragma unroll
    for (int off = 1; off <= 2; off <<= 1) {
        #pragma unroll
        for (int T = 0; T < 2; T++)
            #pragma unroll
            for (int r = 0; r < 2; r++) {
                float other[TOPK];
                #pragma unroll
                for (int k = 0; k < TOPK; k++)
                    other[k] = __shfl_xor_sync(0xffffffffu, top[T][r][k], off);
                #pragma unroll
                for (int k = 0; k < TOPK; k++) ins5(top[T][r], other[k]);
            }
    }

    __syncthreads();
    float (*cand)[21] = (float(*)[21])&SM[0][0][0];   // cand[64][21] = 5.4KB
    if ((lane & 3) == 0) {
        #pragma unroll
        for (int T = 0; T < 2; T++)
            #pragma unroll
            for (int r = 0; r < 2; r++) {
                int row = 32*wm + 16*T + 8*r + qrow;
                #pragma unroll
                for (int k = 0; k < TOPK; k++)
                    cand[row][wn*TOPK + k] = top[T][r][k];
            }
    }
    __syncthreads();

    float rowsum = 0.f;
    if (t < 64) {
        if (h0 + t < HWC) {
            float t5[TOPK];
            #pragma unroll
            for (int k = 0; k < TOPK; k++) t5[k] = -FLT_MAX;
            #pragma unroll
            for (int i = 0; i < 20; i++) ins5(t5, cand[t][i]);
            rowsum = t5[0] + t5[1] + t5[2] + t5[3] + t5[4];
        }
        #pragma unroll
        for (int o = 16; o; o >>= 1) rowsum += __shfl_xor_sync(0xffffffffu, rowsum, o);
        if ((t & 31) == 0) red[t >> 5] = rowsum;
    }
    __syncthreads();
    if (t == 0) g_pix[((size_t)bq*WAYS + w)*NTILE + tile] = red[0] + red[1];
}

// ---------------- BN (batch stats) + dilated conv ----------------
__global__ void __launch_bounds__(256) kfin_kernel(const float* __restrict__ gamma,
                                                   const float* __restrict__ beta,
                                                   const float* __restrict__ cw,
                                                   float* __restrict__ out) {
    const int b = blockIdx.x;
    __shared__ float f[QN][LFE];
    __shared__ float mu[LFE], iv[LFE];
    const int t = threadIdx.x;
    for (int i = t; i < QN * WAYS; i += 256) {
        int q = i / WAYS, w = i - q * WAYS;
        const float* fr = &g_feats[(b*QN + q)*LFE];
        f[q][w]     = fr[w];
        f[q][5 + w] = fr[5 + w];
        float s = 0.f;
        #pragma unroll
        for (int j = 0; j < NTILE; j++)
            s += g_pix[((size_t)(b*QN + q)*WAYS + w)*NTILE + j];
        f[q][10 + w] = s;
    }
    __syncthreads();
    if (t < LFE) {
        float m = 0.f;
        for (int q = 0; q < QN; q++) m += f[q][t];
        m *= (1.0f / QN);
        float v = 0.f;
        for (int q = 0; q < QN; q++) { float d = f[q][t] - m; v = fmaf(d, d, v); }
        v *= (1.0f / QN);
        mu[t] = m;
        iv[t] = 1.0f / sqrtf(v + 1e-5f);
    }
    __syncthreads();
    float w0 = cw[0], w1 = cw[1], w2 = cw[2];
    for (int i = t; i < QN * WAYS; i += 256) {
        int q = i / WAYS, c = i - q * WAYS;
        float b0 = (f[q][c]      - mu[c])      * iv[c]      * gamma[c]      + beta[c];
        float b1 = (f[q][c + 5]  - mu[c + 5])  * iv[c + 5]  * gamma[c + 5]  + beta[c + 5];
        float b2 = (f[q][c + 10] - mu[c + 10]) * iv[c + 10] * gamma[c + 10] + beta[c + 10];
        out[(b*QN + q)*WAYS + c] = w0*b0 + w1*b1 + w2*b2;
    }
}

// ---------------- launch ----------------
extern "C" void kernel_launch(void* const* d_in, const int* in_sizes, int n_in,
                              void* d_out, int out_size) {
    const float* q     = (const float*)d_in[0];
    const float* s     = (const float*)d_in[1];
    const float* gamma = (const float*)d_in[2];
    const float* beta  = (const float*)d_in[3];
    const float* cw    = (const float*)d_in[4];
    float* out = (float*)d_out;

    knorm_kernel<0><<<BB*QN, 256>>>(q);
    knorm_kernel<1><<<BB*NSUP, 256>>>(s);
    kcos_kernel<<<BB, 256>>>();
    kchan_kernel<<<dim3(20, QN, BB), 256>>>();
    kpix_kernel<<<dim3(NTILE, WAYS, BB*QN), 256>>>();
    kmerge_kernel<<<BB*QN*WAYS, 64>>>();
    kfin_kernel<<<BB, 256>>>(gamma, beta, cw, out);
}